// round 1
// baseline (speedup 1.0000x reference)
#include <cuda_runtime.h>

#define NSEQ   2048
#define CDIM   1024
#define HEADS  16
#define HD     64
#define BATCH  4
#define BH     (BATCH*HEADS)
#define MTOT   (BATCH*NSEQ)

// -------- scratch (no allocations allowed) --------
__device__ float g_q[(size_t)BH * NSEQ * HD];        // [b,h,n,d]
__device__ float g_k[(size_t)BH * NSEQ * HD];
__device__ float g_v[(size_t)BH * NSEQ * HD];
__device__ float g_ao[(size_t)BATCH * NSEQ * CDIM];  // attention out, [B,N,C]
__device__ float g_msum[BATCH];

// ======================= mask sum: s[b] = sum_n mWin^2 =======================
__global__ void masksum_kernel(const float* __restrict__ mWin) {
    int b = blockIdx.x;
    float s = 0.f;
    for (int i = threadIdx.x; i < NSEQ; i += blockDim.x) {
        float v = mWin[(size_t)b * NSEQ + i];
        s += v * v;
    }
    #pragma unroll
    for (int o = 16; o; o >>= 1) s += __shfl_xor_sync(0xffffffffu, s, o);
    __shared__ float sm[8];
    if ((threadIdx.x & 31) == 0) sm[threadIdx.x >> 5] = s;
    __syncthreads();
    if (threadIdx.x < 8) {
        float t = sm[threadIdx.x];
        #pragma unroll
        for (int o = 4; o; o >>= 1) t += __shfl_xor_sync(0xffu, t, o);
        if (threadIdx.x == 0) g_msum[b] = t;
    }
}

// ======================= tiled SGEMM (NT): C[m,n] = sum_k A[m,k]*B[n,k] =======
// MODE 0: QKV gemm. epilogue: *mask (and *scale for q), scatter to g_q/g_k/g_v.
// MODE 1: proj gemm. A is g_ao (param ignored), epilogue adds bias, writes out.
#define BM 128
#define BN 128
#define BK 16

template <int MODE>
__global__ __launch_bounds__(256, 1) void sgemm_kernel(
    const float* __restrict__ Ain, const float* __restrict__ B, int K,
    const float* __restrict__ mask, const float* __restrict__ bias,
    float* __restrict__ out)
{
    __shared__ float As[BK][BM];
    __shared__ float Bs[BK][BN];

    const float* A = (MODE == 1) ? (const float*)g_ao : Ain;

    const int bm  = blockIdx.y * BM;
    const int bn  = blockIdx.x * BN;
    const int tid = threadIdx.x;
    const int ty  = tid >> 4;         // 0..15
    const int tx  = tid & 15;         // 0..15
    const int lr  = tid >> 2;         // 0..63
    const int lc  = (tid & 3) * 4;    // 0,4,8,12

    const float* Ap = A + (size_t)(bm + lr) * K + lc;
    const float* Bp = B + (size_t)(bn + lr) * K + lc;

    float acc[8][8];
    #pragma unroll
    for (int i = 0; i < 8; i++)
        #pragma unroll
        for (int j = 0; j < 8; j++) acc[i][j] = 0.f;

    for (int k0 = 0; k0 < K; k0 += BK) {
        float4 a0 = *(const float4*)(Ap);
        float4 a1 = *(const float4*)(Ap + (size_t)64 * K);
        float4 b0 = *(const float4*)(Bp);
        float4 b1 = *(const float4*)(Bp + (size_t)64 * K);
        __syncthreads();
        As[lc + 0][lr]      = a0.x; As[lc + 1][lr]      = a0.y;
        As[lc + 2][lr]      = a0.z; As[lc + 3][lr]      = a0.w;
        As[lc + 0][lr + 64] = a1.x; As[lc + 1][lr + 64] = a1.y;
        As[lc + 2][lr + 64] = a1.z; As[lc + 3][lr + 64] = a1.w;
        Bs[lc + 0][lr]      = b0.x; Bs[lc + 1][lr]      = b0.y;
        Bs[lc + 2][lr]      = b0.z; Bs[lc + 3][lr]      = b0.w;
        Bs[lc + 0][lr + 64] = b1.x; Bs[lc + 1][lr + 64] = b1.y;
        Bs[lc + 2][lr + 64] = b1.z; Bs[lc + 3][lr + 64] = b1.w;
        __syncthreads();
        #pragma unroll
        for (int kk = 0; kk < BK; kk++) {
            float af[8], bf[8];
            *(float4*)(af + 0) = *(const float4*)&As[kk][ty * 8];
            *(float4*)(af + 4) = *(const float4*)&As[kk][ty * 8 + 4];
            *(float4*)(bf + 0) = *(const float4*)&Bs[kk][tx * 8];
            *(float4*)(bf + 4) = *(const float4*)&Bs[kk][tx * 8 + 4];
            #pragma unroll
            for (int i = 0; i < 8; i++)
                #pragma unroll
                for (int j = 0; j < 8; j++)
                    acc[i][j] += af[i] * bf[j];
        }
        Ap += BK;
        Bp += BK;
    }

    if (MODE == 0) {
        const float SCALE = 0.125f;  // hd^-0.5
        #pragma unroll
        for (int i = 0; i < 8; i++) {
            int m  = bm + ty * 8 + i;
            int b  = m >> 11;        // /2048
            int nq = m & 2047;
            float mk = mask[m];
            #pragma unroll
            for (int j4 = 0; j4 < 8; j4 += 4) {
                int col   = bn + tx * 8 + j4;
                int which = col >> 10;
                int c     = col & 1023;
                int h     = c >> 6;
                int d     = c & 63;
                float f = mk * (which == 0 ? SCALE : 1.0f);
                float4 v;
                v.x = acc[i][j4 + 0] * f;
                v.y = acc[i][j4 + 1] * f;
                v.z = acc[i][j4 + 2] * f;
                v.w = acc[i][j4 + 3] * f;
                float* dst = (which == 0) ? g_q : ((which == 1) ? g_k : g_v);
                *(float4*)(dst + (((size_t)(b * HEADS + h) * NSEQ + nq) * HD + d)) = v;
            }
        }
    } else {
        #pragma unroll
        for (int i = 0; i < 8; i++) {
            int m = bm + ty * 8 + i;
            #pragma unroll
            for (int j4 = 0; j4 < 8; j4 += 4) {
                int col = bn + tx * 8 + j4;
                float4 bb = *(const float4*)&bias[col];
                float4 v;
                v.x = acc[i][j4 + 0] + bb.x;
                v.y = acc[i][j4 + 1] + bb.y;
                v.z = acc[i][j4 + 2] + bb.z;
                v.w = acc[i][j4 + 3] + bb.w;
                *(float4*)(out + (size_t)m * CDIM + col) = v;
            }
        }
    }
}

// ======================= attention =======================
// One query row per thread, 256 rows per block, stream K/V in 32-row tiles.
// No max subtraction: logits are O(1) std-normal-ish, exp stays in fp32 range,
// and masked-query rows reproduce the reference's uniform-softmax behavior.
__global__ __launch_bounds__(256, 1) void attn_kernel(const float* __restrict__ mWin) {
    __shared__ float Ks[32][HD];
    __shared__ float Vs[32][HD];

    const int bh = blockIdx.y;        // b*16+h
    const int b  = bh >> 4;
    const int nq = blockIdx.x * 256 + threadIdx.x;

    const float* qp = g_q + ((size_t)bh * NSEQ + nq) * HD;
    float q[HD], o[HD];
    #pragma unroll
    for (int d = 0; d < HD; d += 4) {
        float4 t = *(const float4*)(qp + d);
        q[d] = t.x; q[d + 1] = t.y; q[d + 2] = t.z; q[d + 3] = t.w;
        o[d] = 0.f; o[d + 1] = 0.f; o[d + 2] = 0.f; o[d + 3] = 0.f;
    }
    float den = 0.f;

    const float* kb = g_k + (size_t)bh * NSEQ * HD;
    const float* vb = g_v + (size_t)bh * NSEQ * HD;
    const int lr = threadIdx.x >> 3;       // 0..31
    const int lc = (threadIdx.x & 7) * 8;  // 0..56

    for (int t = 0; t < NSEQ; t += 32) {
        __syncthreads();
        const float* ksrc = kb + (size_t)(t + lr) * HD + lc;
        const float* vsrc = vb + (size_t)(t + lr) * HD + lc;
        *(float4*)&Ks[lr][lc]     = *(const float4*)(ksrc);
        *(float4*)&Ks[lr][lc + 4] = *(const float4*)(ksrc + 4);
        *(float4*)&Vs[lr][lc]     = *(const float4*)(vsrc);
        *(float4*)&Vs[lr][lc + 4] = *(const float4*)(vsrc + 4);
        __syncthreads();
        #pragma unroll 2
        for (int j = 0; j < 32; j++) {
            float s0 = 0.f, s1 = 0.f, s2 = 0.f, s3 = 0.f;
            #pragma unroll
            for (int d = 0; d < HD; d += 16) {
                float4 k0 = *(const float4*)&Ks[j][d];
                float4 k1 = *(const float4*)&Ks[j][d + 4];
                float4 k2 = *(const float4*)&Ks[j][d + 8];
                float4 k3 = *(const float4*)&Ks[j][d + 12];
                s0 += q[d + 0] * k0.x + q[d + 1] * k0.y + q[d + 2] * k0.z + q[d + 3] * k0.w;
                s1 += q[d + 4] * k1.x + q[d + 5] * k1.y + q[d + 6] * k1.z + q[d + 7] * k1.w;
                s2 += q[d + 8] * k2.x + q[d + 9] * k2.y + q[d +10] * k2.z + q[d +11] * k2.w;
                s3 += q[d +12] * k3.x + q[d +13] * k3.y + q[d +14] * k3.z + q[d +15] * k3.w;
            }
            float p = __expf((s0 + s1) + (s2 + s3));
            den += p;
            #pragma unroll
            for (int d = 0; d < HD; d += 4) {
                float4 vv = *(const float4*)&Vs[j][d];
                o[d]     += p * vv.x;
                o[d + 1] += p * vv.y;
                o[d + 2] += p * vv.z;
                o[d + 3] += p * vv.w;
            }
        }
    }

    float mk  = mWin[(size_t)b * NSEQ + nq];
    float sc  = 1.f / (den * (mk * g_msum[b] + 1e-6f));
    float* op = g_ao + ((size_t)(b * NSEQ + nq) * CDIM) + (bh & 15) * HD;
    #pragma unroll
    for (int d = 0; d < HD; d += 4) {
        float4 v;
        v.x = o[d] * sc; v.y = o[d + 1] * sc;
        v.z = o[d + 2] * sc; v.w = o[d + 3] * sc;
        *(float4*)(op + d) = v;
    }
}

// ======================= launch =======================
extern "C" void kernel_launch(void* const* d_in, const int* in_sizes, int n_in,
                              void* d_out, int out_size) {
    const float* x      = (const float*)d_in[0];
    const float* mWin   = (const float*)d_in[1];
    const float* qkv_w  = (const float*)d_in[2];
    const float* proj_w = (const float*)d_in[3];
    const float* proj_b = (const float*)d_in[4];
    float* out = (float*)d_out;

    masksum_kernel<<<BATCH, 256>>>(mWin);

    // qkv = x @ qkv_w^T  (M=8192, N=3072, K=1024), fused mask/scale/scatter
    sgemm_kernel<0><<<dim3(3 * CDIM / BN, MTOT / BM), 256>>>(
        x, qkv_w, CDIM, mWin, nullptr, nullptr);

    // attention + 1/(den*(m*sum+eps)) fused
    attn_kernel<<<dim3(NSEQ / 256, BH), 256>>>(mWin);

    // out = ao @ proj_w^T + proj_b  (M=8192, N=1024, K=1024)
    sgemm_kernel<1><<<dim3(CDIM / BN, MTOT / BM), 256>>>(
        nullptr, proj_w, CDIM, nullptr, proj_b, out);
}

// round 7
// speedup vs baseline: 1.2306x; 1.2306x over previous
#include <cuda_runtime.h>
#include <cuda_bf16.h>
#include <mma.h>

using namespace nvcuda;

#define NSEQ 2048
#define CDIM 1024
#define HEADS 16
#define HD 64
#define BATCH 4
#define BH (BATCH*HEADS)
#define MTOT (BATCH*NSEQ)
#define KC 32
#define PADK 40

__device__ float g_q[(size_t)BH*NSEQ*HD];
__device__ float g_k[(size_t)BH*NSEQ*HD];
__device__ float g_v[(size_t)BH*NSEQ*HD];
__device__ float g_ao[(size_t)BATCH*NSEQ*CDIM];
__device__ float g_msum[BATCH];

__global__ void masksum_kernel(const float* __restrict__ mWin) {
    int b = blockIdx.x;
    float s = 0.f;
    for (int i = threadIdx.x; i < NSEQ; i += blockDim.x) {
        float v = mWin[b*NSEQ + i];
        s += v*v;
    }
    for (int o = 16; o; o >>= 1) s += __shfl_xor_sync(~0u, s, o);
    __shared__ float sm[8];
    if ((threadIdx.x & 31) == 0) sm[threadIdx.x >> 5] = s;
    __syncthreads();
    if (threadIdx.x < 8) {
        float t = sm[threadIdx.x];
        for (int o = 4; o; o >>= 1) t += __shfl_xor_sync(0xffu, t, o);
        if (threadIdx.x == 0) g_msum[b] = t;
    }
}

// split fp32 pair into hi/lo bf16x2
__device__ __forceinline__ void split2(float a, float b, __nv_bfloat162& hi, __nv_bfloat162& lo) {
    __nv_bfloat16 ha = __float2bfloat16_rn(a);
    __nv_bfloat16 hb = __float2bfloat16_rn(b);
    hi = __halves2bfloat162(ha, hb);
    lo = __halves2bfloat162(__float2bfloat16_rn(a - __bfloat162float(ha)),
                            __float2bfloat16_rn(b - __bfloat162float(hb)));
}

typedef wmma::fragment<wmma::matrix_a, 16, 16, 16, __nv_bfloat16, wmma::row_major> FragA;
typedef wmma::fragment<wmma::matrix_b, 16, 16, 16, __nv_bfloat16, wmma::col_major> FragB;
typedef wmma::fragment<wmma::accumulator, 16, 16, 16, float> FragC;

// NT gemm C[m,n]=sum_k A[m,k]B[n,k], bf16-split via WMMA tensor cores.
// MODE 0: qkv (mask/scale/scatter to g_q/g_k/g_v). MODE 1: proj (bias, d_out).
template <int MODE>
__global__ __launch_bounds__(256, 1) void wmma_gemm(
    const float* __restrict__ Ain, const float* __restrict__ B, int K,
    const float* __restrict__ mask, const float* __restrict__ bias, float* __restrict__ out)
{
    __shared__ __align__(16) __nv_bfloat16 Ah[128*PADK];
    __shared__ __align__(16) __nv_bfloat16 Al[128*PADK];
    __shared__ __align__(16) __nv_bfloat16 Bh2[128*PADK];
    __shared__ __align__(16) __nv_bfloat16 Bl2[128*PADK];

    const float* A = (MODE == 1) ? (const float*)g_ao : Ain;
    const int bm = blockIdx.y*128, bn = blockIdx.x*128;
    const int tid = threadIdx.x, lane = tid & 31, wid = tid >> 5;
    const int wm = (wid >> 2)*64;   // warp m offset: 0 or 64
    const int wn = (wid & 3)*32;    // warp n offset: 0,32,64,96
    const int lr = tid >> 3, lc = (tid & 7)*4;

    FragC acc[4][2];
    for (int mi = 0; mi < 4; mi++)
        for (int ni = 0; ni < 2; ni++)
            wmma::fill_fragment(acc[mi][ni], 0.f);

    for (int k0 = 0; k0 < K; k0 += KC) {
        float4 av[4], bv[4];
        #pragma unroll
        for (int j = 0; j < 4; j++) {
            int row = lr + j*32;
            av[j] = *(const float4*)(A + (size_t)(bm + row)*K + k0 + lc);
            bv[j] = *(const float4*)(B + (size_t)(bn + row)*K + k0 + lc);
        }
        __syncthreads();
        #pragma unroll
        for (int j = 0; j < 4; j++) {
            int base = (lr + j*32)*PADK + lc;
            __nv_bfloat162 h0, l0, h1, l1;
            split2(av[j].x, av[j].y, h0, l0);
            split2(av[j].z, av[j].w, h1, l1);
            *(__nv_bfloat162*)&Ah[base] = h0;
            *(__nv_bfloat162*)&Ah[base+2] = h1;
            *(__nv_bfloat162*)&Al[base] = l0;
            *(__nv_bfloat162*)&Al[base+2] = l1;
            split2(bv[j].x, bv[j].y, h0, l0);
            split2(bv[j].z, bv[j].w, h1, l1);
            *(__nv_bfloat162*)&Bh2[base] = h0;
            *(__nv_bfloat162*)&Bh2[base+2] = h1;
            *(__nv_bfloat162*)&Bl2[base] = l0;
            *(__nv_bfloat162*)&Bl2[base+2] = l1;
        }
        __syncthreads();
        #pragma unroll
        for (int ks = 0; ks < KC; ks += 16) {
            FragA fah[4], fal[4];
            FragB fbh[2], fbl[2];
            #pragma unroll
            for (int mi = 0; mi < 4; mi++) {
                int ao = (wm + mi*16)*PADK + ks;
                wmma::load_matrix_sync(fah[mi], &Ah[ao], PADK);
                wmma::load_matrix_sync(fal[mi], &Al[ao], PADK);
            }
            #pragma unroll
            for (int ni = 0; ni < 2; ni++) {
                int bo = (wn + ni*16)*PADK + ks;
                wmma::load_matrix_sync(fbh[ni], &Bh2[bo], PADK);
                wmma::load_matrix_sync(fbl[ni], &Bl2[bo], PADK);
            }
            #pragma unroll
            for (int mi = 0; mi < 4; mi++) {
                #pragma unroll
                for (int ni = 0; ni < 2; ni++) {
                    wmma::mma_sync(acc[mi][ni], fah[mi], fbh[ni], acc[mi][ni]);
                    wmma::mma_sync(acc[mi][ni], fah[mi], fbl[ni], acc[mi][ni]);
                    wmma::mma_sync(acc[mi][ni], fal[mi], fbh[ni], acc[mi][ni]);
                }
            }
        }
    }

    // epilogue via per-warp smem staging (alias the A-hi tile)
    __syncthreads();
    float* stage = (float*)Ah;
    float* ws = stage + wid*256;
    const int srow = lane >> 1;
    const int scol = (lane & 1)*8;
    for (int mi = 0; mi < 4; mi++) {
        for (int ni = 0; ni < 2; ni++) {
            wmma::store_matrix_sync(ws, acc[mi][ni], 16, wmma::mem_row_major);
            __syncwarp();
            int r = bm + wm + mi*16 + srow;
            int col = bn + wn + ni*16 + scol;
            float4 p0 = *(float4*)&ws[srow*16 + scol];
            float4 p1 = *(float4*)&ws[srow*16 + scol + 4];
            if (MODE == 0) {
                int which = col >> 10, c = col & 1023;
                float f = mask[r]*((which == 0) ? 0.125f : 1.f);
                float* dst = (which == 0) ? g_q : ((which == 1) ? g_k : g_v);
                int b = r >> 11, nq = r & 2047, h = c >> 6, d = c & 63;
                float* dp = dst + ((size_t)(b*HEADS + h)*NSEQ + nq)*HD + d;
                *(float4*)dp = make_float4(p0.x*f, p0.y*f, p0.z*f, p0.w*f);
                *(float4*)(dp+4) = make_float4(p1.x*f, p1.y*f, p1.z*f, p1.w*f);
            } else {
                float4 b0 = *(const float4*)&bias[col];
                float4 b1 = *(const float4*)&bias[col+4];
                float* dp = out + (size_t)r*CDIM + col;
                *(float4*)dp = make_float4(p0.x+b0.x, p0.y+b0.y, p0.z+b0.z, p0.w+b0.w);
                *(float4*)(dp+4) = make_float4(p1.x+b1.x, p1.y+b1.y, p1.z+b1.z, p1.w+b1.w);
            }
            __syncwarp();
        }
    }
}

// attention: one query row per thread, K/V tiles of 32 rows in smem
__global__ __launch_bounds__(256, 1) void attn_kernel(const float* __restrict__ mWin) {
    __shared__ float4 Ks[32][HD/4];
    __shared__ float4 Vs[32][HD/4];
    const int bh = blockIdx.y, b = bh >> 4;
    const int nq = blockIdx.x*256 + threadIdx.x;
    const float4* qp = (const float4*)(g_q + ((size_t)bh*NSEQ + nq)*HD);
    float4 q[HD/4], o[HD/4];
    #pragma unroll
    for (int d = 0; d < HD/4; d++) {
        q[d] = qp[d];
        o[d] = make_float4(0.f, 0.f, 0.f, 0.f);
    }
    float den = 0.f;
    const float4* kb = (const float4*)(g_k + (size_t)bh*NSEQ*HD);
    const float4* vb = (const float4*)(g_v + (size_t)bh*NSEQ*HD);
    const int lr = threadIdx.x >> 3, lc = (threadIdx.x & 7)*2;

    for (int t = 0; t < NSEQ; t += 32) {
        __syncthreads();
        #pragma unroll
        for (int u = 0; u < 2; u++) {
            Ks[lr][lc+u] = kb[(size_t)(t + lr)*(HD/4) + lc + u];
            Vs[lr][lc+u] = vb[(size_t)(t + lr)*(HD/4) + lc + u];
        }
        __syncthreads();
        #pragma unroll 2
        for (int j = 0; j < 32; j++) {
            float s = 0.f;
            #pragma unroll
            for (int d = 0; d < HD/4; d++) {
                float4 kk = Ks[j][d];
                s = fmaf(q[d].x, kk.x, s);
                s = fmaf(q[d].y, kk.y, s);
                s = fmaf(q[d].z, kk.z, s);
                s = fmaf(q[d].w, kk.w, s);
            }
            float p = __expf(s);
            den += p;
            #pragma unroll
            for (int d = 0; d < HD/4; d++) {
                float4 vv = Vs[j][d];
                o[d].x = fmaf(p, vv.x, o[d].x);
                o[d].y = fmaf(p, vv.y, o[d].y);
                o[d].z = fmaf(p, vv.z, o[d].z);
                o[d].w = fmaf(p, vv.w, o[d].w);
            }
        }
    }
    float mk = mWin[b*NSEQ + nq];
    float sc = 1.f/(den*(mk*g_msum[b] + 1e-6f));
    float4* op = (float4*)(g_ao + (size_t)(b*NSEQ + nq)*CDIM + (bh & 15)*HD);
    #pragma unroll
    for (int d = 0; d < HD/4; d++) {
        op[d] = make_float4(o[d].x*sc, o[d].y*sc, o[d].z*sc, o[d].w*sc);
    }
}

extern "C" void kernel_launch(void* const* d_in, const int* in_sizes, int n_in,
                              void* d_out, int out_size) {
    const float* x = (const float*)d_in[0];
    const float* mWin = (const float*)d_in[1];
    const float* qkv_w = (const float*)d_in[2];
    const float* proj_w = (const float*)d_in[3];
    const float* proj_b = (const float*)d_in[4];
    float* out = (float*)d_out;

    masksum_kernel<<<BATCH, 256>>>(mWin);
    wmma_gemm<0><<<dim3(3*CDIM/128, MTOT/128), 256>>>(x, qkv_w, CDIM, mWin, nullptr, nullptr);
    attn_kernel<<<dim3(NSEQ/256, BH), 256>>>(mWin);
    wmma_gemm<1><<<dim3(CDIM/128, MTOT/128), 256>>>(nullptr, proj_w, CDIM, nullptr, proj_b, out);
}

// round 9
// speedup vs baseline: 1.6072x; 1.3061x over previous
#include <cuda_runtime.h>
#include <cuda_bf16.h>
#include <mma.h>

using namespace nvcuda;

#define NSEQ 2048
#define CDIM 1024
#define HEADS 16
#define HD 64
#define BATCH 4
#define BH (BATCH*HEADS)
#define MTOT (BATCH*NSEQ)
#define KC 32
#define PADK 40
#define ATT_LD 80
#define SF_LD 68

__device__ __nv_bfloat16 g_qh[(size_t)BH*NSEQ*HD];
__device__ __nv_bfloat16 g_ql[(size_t)BH*NSEQ*HD];
__device__ __nv_bfloat16 g_kh[(size_t)BH*NSEQ*HD];
__device__ __nv_bfloat16 g_kl[(size_t)BH*NSEQ*HD];
__device__ __nv_bfloat16 g_vh[(size_t)BH*NSEQ*HD];
__device__ __nv_bfloat16 g_vl[(size_t)BH*NSEQ*HD];
__device__ float g_ao[(size_t)BATCH*NSEQ*CDIM];
__device__ float g_msum[BATCH];

__global__ void masksum_kernel(const float* __restrict__ mWin) {
    int b = blockIdx.x;
    float s = 0.f;
    for (int i = threadIdx.x; i < NSEQ; i += blockDim.x) {
        float v = mWin[b*NSEQ + i];
        s += v*v;
    }
    for (int o = 16; o; o >>= 1) s += __shfl_xor_sync(~0u, s, o);
    __shared__ float sm[8];
    if ((threadIdx.x & 31) == 0) sm[threadIdx.x >> 5] = s;
    __syncthreads();
    if (threadIdx.x < 8) {
        float t = sm[threadIdx.x];
        for (int o = 4; o; o >>= 1) t += __shfl_xor_sync(0xffu, t, o);
        if (threadIdx.x == 0) g_msum[b] = t;
    }
}

// split fp32 pair into hi/lo bf16x2
__device__ __forceinline__ void split2(float a, float b, __nv_bfloat162& hi, __nv_bfloat162& lo) {
    __nv_bfloat16 ha = __float2bfloat16_rn(a);
    __nv_bfloat16 hb = __float2bfloat16_rn(b);
    hi = __halves2bfloat162(ha, hb);
    lo = __halves2bfloat162(__float2bfloat16_rn(a - __bfloat162float(ha)),
                            __float2bfloat16_rn(b - __bfloat162float(hb)));
}

// FMA-pipe exp (no MUFU): exp(s) = 2^(s*log2e), degree-5 Taylor in ln2
__device__ __forceinline__ float fexp(float s) {
    s = fminf(fmaxf(s, -60.f), 60.f);
    float y = s * 1.4426950408889634f;
    float n = rintf(y);
    float f = y - n;
    float p = 1.3333558146428443e-3f;
    p = fmaf(p, f, 9.6181291076284772e-3f);
    p = fmaf(p, f, 5.5504108664821580e-2f);
    p = fmaf(p, f, 2.4022650695910072e-1f);
    p = fmaf(p, f, 6.9314718055994531e-1f);
    p = fmaf(p, f, 1.0f);
    int e = (int)n;
    return p * __int_as_float((e + 127) << 23);
}

typedef wmma::fragment<wmma::matrix_a, 16, 16, 16, __nv_bfloat16, wmma::row_major> FA;
typedef wmma::fragment<wmma::matrix_b, 16, 16, 16, __nv_bfloat16, wmma::col_major> FBc;
typedef wmma::fragment<wmma::matrix_b, 16, 16, 16, __nv_bfloat16, wmma::row_major> FBr;
typedef wmma::fragment<wmma::accumulator, 16, 16, 16, float> FC;

// NT gemm C[m,n]=sum_k A[m,k]B[n,k], bf16-split via WMMA tensor cores.
// MODE 0: qkv -> mask/scale then split-write bf16 hi/lo q,k,v.
// MODE 1: proj (A = g_ao) -> bias, write d_out fp32.
template <int MODE>
__global__ __launch_bounds__(256, 1) void wmma_gemm(
    const float* __restrict__ Ain, const float* __restrict__ B, int K,
    const float* __restrict__ mask, const float* __restrict__ bias, float* __restrict__ out)
{
    __shared__ __align__(16) __nv_bfloat16 Ah[128*PADK];
    __shared__ __align__(16) __nv_bfloat16 Al[128*PADK];
    __shared__ __align__(16) __nv_bfloat16 Bh2[128*PADK];
    __shared__ __align__(16) __nv_bfloat16 Bl2[128*PADK];

    const float* A = (MODE == 1) ? (const float*)g_ao : Ain;
    const int bm = blockIdx.y*128, bn = blockIdx.x*128;
    const int tid = threadIdx.x, lane = tid & 31, wid = tid >> 5;
    const int wm = (wid >> 2)*64;
    const int wn = (wid & 3)*32;
    const int lr = tid >> 3, lc = (tid & 7)*4;

    FC acc[4][2];
    for (int mi = 0; mi < 4; mi++)
        for (int ni = 0; ni < 2; ni++)
            wmma::fill_fragment(acc[mi][ni], 0.f);

    for (int k0 = 0; k0 < K; k0 += KC) {
        float4 av[4], bv[4];
        #pragma unroll
        for (int j = 0; j < 4; j++) {
            int row = lr + j*32;
            av[j] = *(const float4*)(A + (size_t)(bm + row)*K + k0 + lc);
            bv[j] = *(const float4*)(B + (size_t)(bn + row)*K + k0 + lc);
        }
        __syncthreads();
        #pragma unroll
        for (int j = 0; j < 4; j++) {
            int base = (lr + j*32)*PADK + lc;
            __nv_bfloat162 h0, l0, h1, l1;
            split2(av[j].x, av[j].y, h0, l0);
            split2(av[j].z, av[j].w, h1, l1);
            *(__nv_bfloat162*)&Ah[base] = h0;
            *(__nv_bfloat162*)&Ah[base+2] = h1;
            *(__nv_bfloat162*)&Al[base] = l0;
            *(__nv_bfloat162*)&Al[base+2] = l1;
            split2(bv[j].x, bv[j].y, h0, l0);
            split2(bv[j].z, bv[j].w, h1, l1);
            *(__nv_bfloat162*)&Bh2[base] = h0;
            *(__nv_bfloat162*)&Bh2[base+2] = h1;
            *(__nv_bfloat162*)&Bl2[base] = l0;
            *(__nv_bfloat162*)&Bl2[base+2] = l1;
        }
        __syncthreads();
        #pragma unroll
        for (int ks = 0; ks < KC; ks += 16) {
            FA fah[4], fal[4];
            FBc fbh[2], fbl[2];
            #pragma unroll
            for (int mi = 0; mi < 4; mi++) {
                int ao = (wm + mi*16)*PADK + ks;
                wmma::load_matrix_sync(fah[mi], &Ah[ao], PADK);
                wmma::load_matrix_sync(fal[mi], &Al[ao], PADK);
            }
            #pragma unroll
            for (int ni = 0; ni < 2; ni++) {
                int bo = (wn + ni*16)*PADK + ks;
                wmma::load_matrix_sync(fbh[ni], &Bh2[bo], PADK);
                wmma::load_matrix_sync(fbl[ni], &Bl2[bo], PADK);
            }
            #pragma unroll
            for (int mi = 0; mi < 4; mi++) {
                #pragma unroll
                for (int ni = 0; ni < 2; ni++) {
                    wmma::mma_sync(acc[mi][ni], fah[mi], fbh[ni], acc[mi][ni]);
                    wmma::mma_sync(acc[mi][ni], fah[mi], fbl[ni], acc[mi][ni]);
                    wmma::mma_sync(acc[mi][ni], fal[mi], fbh[ni], acc[mi][ni]);
                }
            }
        }
    }

    __syncthreads();
    float* stage = (float*)Ah;
    float* ws = stage + wid*256;
    const int srow = lane >> 1;
    const int scol = (lane & 1)*8;
    for (int mi = 0; mi < 4; mi++) {
        for (int ni = 0; ni < 2; ni++) {
            wmma::store_matrix_sync(ws, acc[mi][ni], 16, wmma::mem_row_major);
            __syncwarp();
            int r = bm + wm + mi*16 + srow;
            int col = bn + wn + ni*16 + scol;
            float4 p0 = *(float4*)&ws[srow*16 + scol];
            float4 p1 = *(float4*)&ws[srow*16 + scol + 4];
            if (MODE == 0) {
                int which = col >> 10, c = col & 1023;
                float f = mask[r]*((which == 0) ? 0.125f : 1.f);
                __nv_bfloat16* dh = (which == 0) ? g_qh : ((which == 1) ? g_kh : g_vh);
                __nv_bfloat16* dl = (which == 0) ? g_ql : ((which == 1) ? g_kl : g_vl);
                int b = r >> 11, nq = r & 2047, h2 = c >> 6, d = c & 63;
                size_t off = ((size_t)(b*HEADS + h2)*NSEQ + nq)*HD + d;
                float vals[8];
                vals[0] = p0.x; vals[1] = p0.y; vals[2] = p0.z; vals[3] = p0.w;
                vals[4] = p1.x; vals[5] = p1.y; vals[6] = p1.z; vals[7] = p1.w;
                __nv_bfloat16 hh[8], ll[8];
                #pragma unroll
                for (int j = 0; j < 8; j++) {
                    float v = vals[j]*f;
                    __nv_bfloat16 hv = __float2bfloat16_rn(v);
                    hh[j] = hv;
                    ll[j] = __float2bfloat16_rn(v - __bfloat162float(hv));
                }
                *(uint4*)&dh[off] = *(uint4*)hh;
                *(uint4*)&dl[off] = *(uint4*)ll;
            } else {
                float4 b0 = *(const float4*)&bias[col];
                float4 b1 = *(const float4*)&bias[col+4];
                float* dp = out + (size_t)r*CDIM + col;
                *(float4*)dp = make_float4(p0.x+b0.x, p0.y+b0.y, p0.z+b0.z, p0.w+b0.w);
                *(float4*)(dp+4) = make_float4(p1.x+b1.x, p1.y+b1.y, p1.z+b1.z, p1.w+b1.w);
            }
            __syncwarp();
        }
    }
}

// tensor-core attention: CTA = 64 q-rows of one (b,h), 4 warps, k-tiles of 64.
// S = QK via bf16-split wmma, exp on FMA pipe, P split, O += PV via wmma.
__global__ __launch_bounds__(128, 2) void attn_mma(const float* __restrict__ mWin) {
    extern __shared__ char smraw[];
    __nv_bfloat16* KH = (__nv_bfloat16*)smraw;
    __nv_bfloat16* KL = KH + 64*ATT_LD;
    __nv_bfloat16* VH = KL + 64*ATT_LD;
    __nv_bfloat16* VL = VH + 64*ATT_LD;
    __nv_bfloat16* PH = VL + 64*ATT_LD;
    __nv_bfloat16* PL = PH + 64*ATT_LD;
    float* SF = (float*)(PL + 64*ATT_LD);
    float* DEN = SF + 64*SF_LD;

    const int tid = threadIdx.x, w = tid >> 5;
    const int bh = blockIdx.y, b = bh >> 4, h = bh & 15;
    const int q0 = blockIdx.x*64;
    const size_t base = (size_t)bh*NSEQ*HD;

    FA qfh[4], qfl[4];
    {
        const __nv_bfloat16* qp = g_qh + base + (size_t)(q0 + w*16)*HD;
        const __nv_bfloat16* qp2 = g_ql + base + (size_t)(q0 + w*16)*HD;
        #pragma unroll
        for (int kk = 0; kk < 4; kk++) {
            wmma::load_matrix_sync(qfh[kk], qp + kk*16, HD);
            wmma::load_matrix_sync(qfl[kk], qp2 + kk*16, HD);
        }
    }

    FC o[4];
    #pragma unroll
    for (int i = 0; i < 4; i++) wmma::fill_fragment(o[i], 0.f);
    float den = 0.f;
    const int erow = tid >> 1, ecol = (tid & 1)*32;

    for (int kt = 0; kt < NSEQ; kt += 64) {
        __syncthreads();
        #pragma unroll
        for (int i = 0; i < 16; i++) {
            int idx = tid + i*128;
            int arr = idx >> 9;
            int rem = idx & 511;
            int row = rem >> 3, c4 = rem & 7;
            const __nv_bfloat16* src;
            __nv_bfloat16* dst;
            if (arr == 0) { src = g_kh; dst = KH; }
            else if (arr == 1) { src = g_kl; dst = KL; }
            else if (arr == 2) { src = g_vh; dst = VH; }
            else { src = g_vl; dst = VL; }
            const uint4* s4 = (const uint4*)(src + base + (size_t)(kt + row)*HD);
            *(uint4*)(dst + row*ATT_LD + c4*8) = s4[c4];
        }
        __syncthreads();
        #pragma unroll
        for (int n = 0; n < 4; n++) {
            FC s;
            wmma::fill_fragment(s, 0.f);
            #pragma unroll
            for (int kk = 0; kk < 4; kk++) {
                FBc kbh, kbl;
                wmma::load_matrix_sync(kbh, KH + n*16*ATT_LD + kk*16, ATT_LD);
                wmma::load_matrix_sync(kbl, KL + n*16*ATT_LD + kk*16, ATT_LD);
                wmma::mma_sync(s, qfh[kk], kbh, s);
                wmma::mma_sync(s, qfh[kk], kbl, s);
                wmma::mma_sync(s, qfl[kk], kbh, s);
            }
            wmma::store_matrix_sync(SF + w*16*SF_LD + n*16, s, SF_LD, wmma::mem_row_major);
        }
        __syncthreads();
        #pragma unroll
        for (int j = 0; j < 32; j++) {
            float p = fexp(SF[erow*SF_LD + ecol + j]);
            den += p;
            __nv_bfloat16 ph = __float2bfloat16_rn(p);
            PH[erow*ATT_LD + ecol + j] = ph;
            PL[erow*ATT_LD + ecol + j] = __float2bfloat16_rn(p - __bfloat162float(ph));
        }
        __syncthreads();
        FA pa[4], pb[4];
        #pragma unroll
        for (int kk = 0; kk < 4; kk++) {
            wmma::load_matrix_sync(pa[kk], PH + w*16*ATT_LD + kk*16, ATT_LD);
            wmma::load_matrix_sync(pb[kk], PL + w*16*ATT_LD + kk*16, ATT_LD);
        }
        #pragma unroll
        for (int nd = 0; nd < 4; nd++) {
            #pragma unroll
            for (int kk = 0; kk < 4; kk++) {
                FBr vbh, vbl;
                wmma::load_matrix_sync(vbh, VH + kk*16*ATT_LD + nd*16, ATT_LD);
                wmma::load_matrix_sync(vbl, VL + kk*16*ATT_LD + nd*16, ATT_LD);
                wmma::mma_sync(o[nd], pa[kk], vbh, o[nd]);
                wmma::mma_sync(o[nd], pa[kk], vbl, o[nd]);
                wmma::mma_sync(o[nd], pb[kk], vbh, o[nd]);
            }
        }
    }

    DEN[tid] = den;
    #pragma unroll
    for (int nd = 0; nd < 4; nd++)
        wmma::store_matrix_sync(SF + w*16*SF_LD + nd*16, o[nd], SF_LD, wmma::mem_row_major);
    __syncthreads();
    {
        int nq = q0 + erow;
        float dsum = DEN[erow*2] + DEN[erow*2+1];
        float mk = mWin[b*NSEQ + nq];
        float sc = 1.f/(dsum*(mk*g_msum[b] + 1e-6f));
        float* op = g_ao + (size_t)(b*NSEQ + nq)*CDIM + h*HD + ecol;
        #pragma unroll
        for (int j = 0; j < 32; j += 4) {
            float4 v = *(float4*)&SF[erow*SF_LD + ecol + j];
            *(float4*)&op[j] = make_float4(v.x*sc, v.y*sc, v.z*sc, v.w*sc);
        }
    }
}

extern "C" void kernel_launch(void* const* d_in, const int* in_sizes, int n_in,
                              void* d_out, int out_size) {
    const float* x = (const float*)d_in[0];
    const float* mWin = (const float*)d_in[1];
    const float* qkv_w = (const float*)d_in[2];
    const float* proj_w = (const float*)d_in[3];
    const float* proj_b = (const float*)d_in[4];
    float* out = (float*)d_out;

    const int attn_smem = 6*64*ATT_LD*2 + 64*SF_LD*4 + 128*4;
    cudaFuncSetAttribute(attn_mma, cudaFuncAttributeMaxDynamicSharedMemorySize, attn_smem);

    masksum_kernel<<<BATCH, 256>>>(mWin);
    wmma_gemm<0><<<dim3(3*CDIM/128, MTOT/128), 256>>>(x, qkv_w, CDIM, mWin, nullptr, nullptr);
    attn_mma<<<dim3(NSEQ/64, BH), 128, attn_smem>>>(mWin);
    wmma_gemm<1><<<dim3(CDIM/128, MTOT/128), 256>>>(nullptr, proj_w, CDIM, nullptr, proj_b, out);
}

// round 10
// speedup vs baseline: 1.6775x; 1.0438x over previous
#include <cuda_runtime.h>
#include <cuda_bf16.h>
#include <cuda_pipeline_primitives.h>
#include <mma.h>

using namespace nvcuda;

#define NSEQ 2048
#define CDIM 1024
#define HEADS 16
#define HD 64
#define BATCH 4
#define BH (BATCH*HEADS)
#define MTOT (BATCH*NSEQ)
#define KC 32
#define PADK 40
#define KV_LD 80
#define SF_LD 68
#define KVB 5120
#define BUFH 20480

__device__ __nv_bfloat16 g_qh[(size_t)BH*NSEQ*HD];
__device__ __nv_bfloat16 g_ql[(size_t)BH*NSEQ*HD];
__device__ __nv_bfloat16 g_kh[(size_t)BH*NSEQ*HD];
__device__ __nv_bfloat16 g_kl[(size_t)BH*NSEQ*HD];
__device__ __nv_bfloat16 g_vh[(size_t)BH*NSEQ*HD];
__device__ __nv_bfloat16 g_vl[(size_t)BH*NSEQ*HD];
__device__ float g_ao[(size_t)BATCH*NSEQ*CDIM];
__device__ float g_msum[BATCH];

__global__ void masksum_kernel(const float* __restrict__ mWin) {
    int b = blockIdx.x;
    float s = 0.f;
    for (int i = threadIdx.x; i < NSEQ; i += blockDim.x) {
        float v = mWin[b*NSEQ + i];
        s += v*v;
    }
    for (int o = 16; o; o >>= 1) s += __shfl_xor_sync(~0u, s, o);
    __shared__ float sm[8];
    if ((threadIdx.x & 31) == 0) sm[threadIdx.x >> 5] = s;
    __syncthreads();
    if (threadIdx.x < 8) {
        float t = sm[threadIdx.x];
        for (int o = 4; o; o >>= 1) t += __shfl_xor_sync(0xffu, t, o);
        if (threadIdx.x == 0) g_msum[b] = t;
    }
}

// split fp32 pair into hi/lo bf16x2
__device__ __forceinline__ void split2(float a, float b, __nv_bfloat162& hi, __nv_bfloat162& lo) {
    __nv_bfloat16 ha = __float2bfloat16_rn(a);
    __nv_bfloat16 hb = __float2bfloat16_rn(b);
    hi = __halves2bfloat162(ha, hb);
    lo = __halves2bfloat162(__float2bfloat16_rn(a - __bfloat162float(ha)),
                            __float2bfloat16_rn(b - __bfloat162float(hb)));
}

// FMA-pipe exp (no MUFU)
__device__ __forceinline__ float fexp(float s) {
    s = fminf(fmaxf(s, -60.f), 60.f);
    float y = s * 1.4426950408889634f;
    float n = rintf(y);
    float f = y - n;
    float p = 1.3333558146428443e-3f;
    p = fmaf(p, f, 9.6181291076284772e-3f);
    p = fmaf(p, f, 5.5504108664821580e-2f);
    p = fmaf(p, f, 2.4022650695910072e-1f);
    p = fmaf(p, f, 6.9314718055994531e-1f);
    p = fmaf(p, f, 1.0f);
    int e = (int)n;
    return p * __int_as_float((e + 127) << 23);
}

typedef wmma::fragment<wmma::matrix_a, 16, 16, 16, __nv_bfloat16, wmma::row_major> FA;
typedef wmma::fragment<wmma::matrix_b, 16, 16, 16, __nv_bfloat16, wmma::col_major> FBc;
typedef wmma::fragment<wmma::matrix_b, 16, 16, 16, __nv_bfloat16, wmma::row_major> FBr;
typedef wmma::fragment<wmma::accumulator, 16, 16, 16, float> FC;

// NT gemm, bf16-split via WMMA. MODE 0: qkv split-write. MODE 1: proj.
template <int MODE>
__global__ __launch_bounds__(256, 1) void wmma_gemm(
    const float* __restrict__ Ain, const float* __restrict__ B, int K,
    const float* __restrict__ mask, const float* __restrict__ bias, float* __restrict__ out)
{
    __shared__ __align__(16) __nv_bfloat16 Ah[128*PADK];
    __shared__ __align__(16) __nv_bfloat16 Al[128*PADK];
    __shared__ __align__(16) __nv_bfloat16 Bh2[128*PADK];
    __shared__ __align__(16) __nv_bfloat16 Bl2[128*PADK];

    const float* A = (MODE == 1) ? (const float*)g_ao : Ain;
    const int bm = blockIdx.y*128, bn = blockIdx.x*128;
    const int tid = threadIdx.x, lane = tid & 31, wid = tid >> 5;
    const int wm = (wid >> 2)*64;
    const int wn = (wid & 3)*32;
    const int lr = tid >> 3, lc = (tid & 7)*4;

    FC acc[4][2];
    for (int mi = 0; mi < 4; mi++)
        for (int ni = 0; ni < 2; ni++)
            wmma::fill_fragment(acc[mi][ni], 0.f);

    for (int k0 = 0; k0 < K; k0 += KC) {
        float4 av[4], bv[4];
        #pragma unroll
        for (int j = 0; j < 4; j++) {
            int row = lr + j*32;
            av[j] = *(const float4*)(A + (size_t)(bm + row)*K + k0 + lc);
            bv[j] = *(const float4*)(B + (size_t)(bn + row)*K + k0 + lc);
        }
        __syncthreads();
        #pragma unroll
        for (int j = 0; j < 4; j++) {
            int base = (lr + j*32)*PADK + lc;
            __nv_bfloat162 h0, l0, h1, l1;
            split2(av[j].x, av[j].y, h0, l0);
            split2(av[j].z, av[j].w, h1, l1);
            *(__nv_bfloat162*)&Ah[base] = h0;
            *(__nv_bfloat162*)&Ah[base+2] = h1;
            *(__nv_bfloat162*)&Al[base] = l0;
            *(__nv_bfloat162*)&Al[base+2] = l1;
            split2(bv[j].x, bv[j].y, h0, l0);
            split2(bv[j].z, bv[j].w, h1, l1);
            *(__nv_bfloat162*)&Bh2[base] = h0;
            *(__nv_bfloat162*)&Bh2[base+2] = h1;
            *(__nv_bfloat162*)&Bl2[base] = l0;
            *(__nv_bfloat162*)&Bl2[base+2] = l1;
        }
        __syncthreads();
        #pragma unroll
        for (int ks = 0; ks < KC; ks += 16) {
            FA fah[4], fal[4];
            FBc fbh[2], fbl[2];
            #pragma unroll
            for (int mi = 0; mi < 4; mi++) {
                int ao = (wm + mi*16)*PADK + ks;
                wmma::load_matrix_sync(fah[mi], &Ah[ao], PADK);
                wmma::load_matrix_sync(fal[mi], &Al[ao], PADK);
            }
            #pragma unroll
            for (int ni = 0; ni < 2; ni++) {
                int bo = (wn + ni*16)*PADK + ks;
                wmma::load_matrix_sync(fbh[ni], &Bh2[bo], PADK);
                wmma::load_matrix_sync(fbl[ni], &Bl2[bo], PADK);
            }
            #pragma unroll
            for (int mi = 0; mi < 4; mi++) {
                #pragma unroll
                for (int ni = 0; ni < 2; ni++) {
                    wmma::mma_sync(acc[mi][ni], fah[mi], fbh[ni], acc[mi][ni]);
                    wmma::mma_sync(acc[mi][ni], fah[mi], fbl[ni], acc[mi][ni]);
                    wmma::mma_sync(acc[mi][ni], fal[mi], fbh[ni], acc[mi][ni]);
                }
            }
        }
    }

    __syncthreads();
    float* stage = (float*)Ah;
    float* ws = stage + wid*256;
    const int srow = lane >> 1;
    const int scol = (lane & 1)*8;
    for (int mi = 0; mi < 4; mi++) {
        for (int ni = 0; ni < 2; ni++) {
            wmma::store_matrix_sync(ws, acc[mi][ni], 16, wmma::mem_row_major);
            __syncwarp();
            int r = bm + wm + mi*16 + srow;
            int col = bn + wn + ni*16 + scol;
            float4 p0 = *(float4*)&ws[srow*16 + scol];
            float4 p1 = *(float4*)&ws[srow*16 + scol + 4];
            if (MODE == 0) {
                int which = col >> 10, c = col & 1023;
                float f = mask[r]*((which == 0) ? 0.125f : 1.f);
                __nv_bfloat16* dh = (which == 0) ? g_qh : ((which == 1) ? g_kh : g_vh);
                __nv_bfloat16* dl = (which == 0) ? g_ql : ((which == 1) ? g_kl : g_vl);
                int b = r >> 11, nq = r & 2047, h2 = c >> 6, d = c & 63;
                size_t off = ((size_t)(b*HEADS + h2)*NSEQ + nq)*HD + d;
                float vals[8];
                vals[0] = p0.x; vals[1] = p0.y; vals[2] = p0.z; vals[3] = p0.w;
                vals[4] = p1.x; vals[5] = p1.y; vals[6] = p1.z; vals[7] = p1.w;
                __nv_bfloat16 hh[8], ll[8];
                #pragma unroll
                for (int j = 0; j < 8; j++) {
                    float v = vals[j]*f;
                    __nv_bfloat16 hv = __float2bfloat16_rn(v);
                    hh[j] = hv;
                    ll[j] = __float2bfloat16_rn(v - __bfloat162float(hv));
                }
                *(uint4*)&dh[off] = *(uint4*)hh;
                *(uint4*)&dl[off] = *(uint4*)ll;
            } else {
                float4 b0 = *(const float4*)&bias[col];
                float4 b1 = *(const float4*)&bias[col+4];
                float* dp = out + (size_t)r*CDIM + col;
                *(float4*)dp = make_float4(p0.x+b0.x, p0.y+b0.y, p0.z+b0.z, p0.w+b0.w);
                *(float4*)(dp+4) = make_float4(p1.x+b1.x, p1.y+b1.y, p1.z+b1.z, p1.w+b1.w);
            }
            __syncwarp();
        }
    }
}

// prefetch one 64-row k-tile (KH,KL,VH,VL) into a smem buffer via cp.async
__device__ __forceinline__ void prefetch_tile(int tid, size_t base, int kt, __nv_bfloat16* buf) {
    #pragma unroll
    for (int t = 0; t < 8; t++) {
        int c = tid + t*256;
        int arr = c >> 9, rem = c & 511;
        int row = rem >> 3, seg = rem & 7;
        const __nv_bfloat16* src;
        if (arr == 0) src = g_kh;
        else if (arr == 1) src = g_kl;
        else if (arr == 2) src = g_vh;
        else src = g_vl;
        __pipeline_memcpy_async(buf + arr*KVB + row*KV_LD + seg*8,
                                src + base + (size_t)(kt + row)*HD + seg*8, 16);
    }
}

// tensor-core attention v2: 256 thr / 8 warps, 128 q-rows per CTA,
// double-buffered cp.async K/V tiles, warp-local S/exp/P phases.
__global__ __launch_bounds__(256, 1) void attn_mma(const float* __restrict__ mWin) {
    extern __shared__ char smraw[];
    __nv_bfloat16* KV = (__nv_bfloat16*)smraw;         // [2][4][64*KV_LD]
    __nv_bfloat16* PH = KV + 2*BUFH;                   // [128*KV_LD]
    __nv_bfloat16* PL = PH + 128*KV_LD;
    float* SF = (float*)(PL + 128*KV_LD);              // [128*SF_LD]
    float* DEN = SF + 128*SF_LD;                       // [256]

    const int tid = threadIdx.x, w = tid >> 5;
    const int bh = blockIdx.y, b = bh >> 4, h = bh & 15;
    const int q0 = blockIdx.x*128;
    const size_t base = (size_t)bh*NSEQ*HD;

    FA qfh[4], qfl[4];
    {
        const __nv_bfloat16* qp = g_qh + base + (size_t)(q0 + w*16)*HD;
        const __nv_bfloat16* qp2 = g_ql + base + (size_t)(q0 + w*16)*HD;
        #pragma unroll
        for (int kk = 0; kk < 4; kk++) {
            wmma::load_matrix_sync(qfh[kk], qp + kk*16, HD);
            wmma::load_matrix_sync(qfl[kk], qp2 + kk*16, HD);
        }
    }

    FC o[4];
    #pragma unroll
    for (int i = 0; i < 4; i++) wmma::fill_fragment(o[i], 0.f);
    float den = 0.f;
    const int erow = tid >> 1, ecol = (tid & 1)*32;

    prefetch_tile(tid, base, 0, KV);
    __pipeline_commit();

    for (int it = 0; it < 32; it++) {
        __syncthreads();   // everyone done reading the buffer we now prefetch into
        if (it + 1 < 32) prefetch_tile(tid, base, (it+1)*64, KV + ((it+1)&1)*BUFH);
        __pipeline_commit();
        __pipeline_wait_prior(1);   // current tile's data arrived
        __syncthreads();            // ...and visible to all warps

        __nv_bfloat16* KHb = KV + (it&1)*BUFH;
        __nv_bfloat16* KLb = KHb + KVB;
        __nv_bfloat16* VHb = KHb + 2*KVB;
        __nv_bfloat16* VLb = KHb + 3*KVB;

        // S = Q K^T (warp-local 16 q-rows)
        #pragma unroll
        for (int n = 0; n < 4; n++) {
            FC s;
            wmma::fill_fragment(s, 0.f);
            #pragma unroll
            for (int kk = 0; kk < 4; kk++) {
                FBc kbh, kbl;
                wmma::load_matrix_sync(kbh, KHb + n*16*KV_LD + kk*16, KV_LD);
                wmma::load_matrix_sync(kbl, KLb + n*16*KV_LD + kk*16, KV_LD);
                wmma::mma_sync(s, qfh[kk], kbh, s);
                wmma::mma_sync(s, qfh[kk], kbl, s);
                wmma::mma_sync(s, qfl[kk], kbh, s);
            }
            wmma::store_matrix_sync(SF + w*16*SF_LD + n*16, s, SF_LD, wmma::mem_row_major);
        }
        __syncwarp();

        // exp + P split (rows are warp-local: erow in warp w's 16 rows)
        #pragma unroll
        for (int j = 0; j < 32; j++) {
            float p = fexp(SF[erow*SF_LD + ecol + j]);
            den += p;
            __nv_bfloat16 ph = __float2bfloat16_rn(p);
            PH[erow*KV_LD + ecol + j] = ph;
            PL[erow*KV_LD + ecol + j] = __float2bfloat16_rn(p - __bfloat162float(ph));
        }
        __syncwarp();

        // O += P V (P warp-local, V shared)
        FA pa[4], pb[4];
        #pragma unroll
        for (int kk = 0; kk < 4; kk++) {
            wmma::load_matrix_sync(pa[kk], PH + w*16*KV_LD + kk*16, KV_LD);
            wmma::load_matrix_sync(pb[kk], PL + w*16*KV_LD + kk*16, KV_LD);
        }
        #pragma unroll
        for (int nd = 0; nd < 4; nd++) {
            #pragma unroll
            for (int kk = 0; kk < 4; kk++) {
                FBr vbh, vbl;
                wmma::load_matrix_sync(vbh, VHb + kk*16*KV_LD + nd*16, KV_LD);
                wmma::load_matrix_sync(vbl, VLb + kk*16*KV_LD + nd*16, KV_LD);
                wmma::mma_sync(o[nd], pa[kk], vbh, o[nd]);
                wmma::mma_sync(o[nd], pa[kk], vbl, o[nd]);
                wmma::mma_sync(o[nd], pb[kk], vbh, o[nd]);
            }
        }
    }

    DEN[tid] = den;
    #pragma unroll
    for (int nd = 0; nd < 4; nd++)
        wmma::store_matrix_sync(SF + w*16*SF_LD + nd*16, o[nd], SF_LD, wmma::mem_row_major);
    __syncthreads();
    {
        int nq = q0 + erow;
        float dsum = DEN[erow*2] + DEN[erow*2+1];
        float mk = mWin[b*NSEQ + nq];
        float sc = 1.f/(dsum*(mk*g_msum[b] + 1e-6f));
        float* op = g_ao + (size_t)(b*NSEQ + nq)*CDIM + h*HD + ecol;
        #pragma unroll
        for (int j = 0; j < 32; j += 4) {
            float4 v = *(float4*)&SF[erow*SF_LD + ecol + j];
            *(float4*)&op[j] = make_float4(v.x*sc, v.y*sc, v.z*sc, v.w*sc);
        }
    }
}

extern "C" void kernel_launch(void* const* d_in, const int* in_sizes, int n_in,
                              void* d_out, int out_size) {
    const float* x = (const float*)d_in[0];
    const float* mWin = (const float*)d_in[1];
    const float* qkv_w = (const float*)d_in[2];
    const float* proj_w = (const float*)d_in[3];
    const float* proj_b = (const float*)d_in[4];
    float* out = (float*)d_out;

    const int attn_smem = (2*BUFH + 2*128*KV_LD)*2 + 128*SF_LD*4 + 256*4;
    cudaFuncSetAttribute(attn_mma, cudaFuncAttributeMaxDynamicSharedMemorySize, attn_smem);

    masksum_kernel<<<BATCH, 256>>>(mWin);
    wmma_gemm<0><<<dim3(3*CDIM/128, MTOT/128), 256>>>(x, qkv_w, CDIM, mWin, nullptr, nullptr);
    attn_mma<<<dim3(NSEQ/128, BH), 256, attn_smem>>>(mWin);
    wmma_gemm<1><<<dim3(CDIM/128, MTOT/128), 256>>>(nullptr, proj_w, CDIM, nullptr, proj_b, out);
}

// round 12
// speedup vs baseline: 1.9485x; 1.1615x over previous
#include <cuda_runtime.h>
#include <cuda_bf16.h>
#include <cuda_pipeline_primitives.h>
#include <mma.h>

using namespace nvcuda;

#define NSEQ 2048
#define CDIM 1024
#define HEADS 16
#define HD 64
#define BATCH 4
#define BH (BATCH*HEADS)
#define MTOT (BATCH*NSEQ)
#define KC 32
#define PADK 40
#define KV_LD 80
#define SF_LD 68
#define KVB 5120
#define BUFH 20480

__device__ __nv_bfloat16 g_qh[(size_t)BH*NSEQ*HD];
__device__ __nv_bfloat16 g_ql[(size_t)BH*NSEQ*HD];
__device__ __nv_bfloat16 g_kh[(size_t)BH*NSEQ*HD];
__device__ __nv_bfloat16 g_kl[(size_t)BH*NSEQ*HD];
__device__ __nv_bfloat16 g_vh[(size_t)BH*NSEQ*HD];
__device__ __nv_bfloat16 g_vl[(size_t)BH*NSEQ*HD];
__device__ float g_ao[(size_t)BATCH*NSEQ*CDIM];
__device__ float g_msum[BATCH];

__global__ void masksum_kernel(const float* __restrict__ mWin) {
    int b = blockIdx.x;
    float s = 0.f;
    for (int i = threadIdx.x; i < NSEQ; i += blockDim.x) {
        float v = mWin[b*NSEQ + i];
        s += v*v;
    }
    for (int o = 16; o; o >>= 1) s += __shfl_xor_sync(~0u, s, o);
    __shared__ float sm[8];
    if ((threadIdx.x & 31) == 0) sm[threadIdx.x >> 5] = s;
    __syncthreads();
    if (threadIdx.x < 8) {
        float t = sm[threadIdx.x];
        for (int o = 4; o; o >>= 1) t += __shfl_xor_sync(0xffu, t, o);
        if (threadIdx.x == 0) g_msum[b] = t;
    }
}

// split fp32 pair into hi/lo bf16x2
__device__ __forceinline__ void split2(float a, float b, __nv_bfloat162& hi, __nv_bfloat162& lo) {
    __nv_bfloat16 ha = __float2bfloat16_rn(a);
    __nv_bfloat16 hb = __float2bfloat16_rn(b);
    hi = __halves2bfloat162(ha, hb);
    lo = __halves2bfloat162(__float2bfloat16_rn(a - __bfloat162float(ha)),
                            __float2bfloat16_rn(b - __bfloat162float(hb)));
}

// FMA-pipe exp (no MUFU)
__device__ __forceinline__ float fexp(float s) {
    s = fminf(fmaxf(s, -60.f), 60.f);
    float y = s * 1.4426950408889634f;
    float n = rintf(y);
    float f = y - n;
    float p = 1.3333558146428443e-3f;
    p = fmaf(p, f, 9.6181291076284772e-3f);
    p = fmaf(p, f, 5.5504108664821580e-2f);
    p = fmaf(p, f, 2.4022650695910072e-1f);
    p = fmaf(p, f, 6.9314718055994531e-1f);
    p = fmaf(p, f, 1.0f);
    int e = (int)n;
    return p * __int_as_float((e + 127) << 23);
}

typedef wmma::fragment<wmma::matrix_a, 16, 16, 16, __nv_bfloat16, wmma::row_major> FA;
typedef wmma::fragment<wmma::matrix_b, 16, 16, 16, __nv_bfloat16, wmma::col_major> FBc;
typedef wmma::fragment<wmma::matrix_b, 16, 16, 16, __nv_bfloat16, wmma::row_major> FBr;
typedef wmma::fragment<wmma::accumulator, 16, 16, 16, float> FC;

// NT gemm, bf16-split via WMMA, register-prefetch one k-chunk ahead.
// MODE 0: qkv split-write. MODE 1: proj.
template <int MODE>
__global__ __launch_bounds__(256, 1) void wmma_gemm(
    const float* __restrict__ Ain, const float* __restrict__ B, int K,
    const float* __restrict__ mask, const float* __restrict__ bias, float* __restrict__ out)
{
    __shared__ __align__(16) __nv_bfloat16 Ah[128*PADK];
    __shared__ __align__(16) __nv_bfloat16 Al[128*PADK];
    __shared__ __align__(16) __nv_bfloat16 Bh2[128*PADK];
    __shared__ __align__(16) __nv_bfloat16 Bl2[128*PADK];

    const float* A = (MODE == 1) ? (const float*)g_ao : Ain;
    const int bm = blockIdx.y*128, bn = blockIdx.x*128;
    const int tid = threadIdx.x, lane = tid & 31, wid = tid >> 5;
    const int wm = (wid >> 2)*64;
    const int wn = (wid & 3)*32;
    const int lr = tid >> 3, lc = (tid & 7)*4;

    FC acc[4][2];
    for (int mi = 0; mi < 4; mi++)
        for (int ni = 0; ni < 2; ni++)
            wmma::fill_fragment(acc[mi][ni], 0.f);

    const float* Abase = A + (size_t)(bm + lr)*K + lc;
    const float* Bbase = B + (size_t)(bn + lr)*K + lc;

    float4 av[4], bv[4];
    #pragma unroll
    for (int j = 0; j < 4; j++) {
        av[j] = *(const float4*)(Abase + (size_t)(j*32)*K);
        bv[j] = *(const float4*)(Bbase + (size_t)(j*32)*K);
    }

    for (int k0 = 0; k0 < K; k0 += KC) {
        __syncthreads();
        #pragma unroll
        for (int j = 0; j < 4; j++) {
            int base = (lr + j*32)*PADK + lc;
            __nv_bfloat162 h0, l0, h1, l1;
            split2(av[j].x, av[j].y, h0, l0);
            split2(av[j].z, av[j].w, h1, l1);
            *(__nv_bfloat162*)&Ah[base] = h0;
            *(__nv_bfloat162*)&Ah[base+2] = h1;
            *(__nv_bfloat162*)&Al[base] = l0;
            *(__nv_bfloat162*)&Al[base+2] = l1;
            split2(bv[j].x, bv[j].y, h0, l0);
            split2(bv[j].z, bv[j].w, h1, l1);
            *(__nv_bfloat162*)&Bh2[base] = h0;
            *(__nv_bfloat162*)&Bh2[base+2] = h1;
            *(__nv_bfloat162*)&Bl2[base] = l0;
            *(__nv_bfloat162*)&Bl2[base+2] = l1;
        }
        __syncthreads();
        // prefetch next chunk while the tensor cores chew on this one
        if (k0 + KC < K) {
            #pragma unroll
            for (int j = 0; j < 4; j++) {
                av[j] = *(const float4*)(Abase + (size_t)(j*32)*K + k0 + KC);
                bv[j] = *(const float4*)(Bbase + (size_t)(j*32)*K + k0 + KC);
            }
        }
        #pragma unroll
        for (int ks = 0; ks < KC; ks += 16) {
            FA fah[4], fal[4];
            FBc fbh[2], fbl[2];
            #pragma unroll
            for (int mi = 0; mi < 4; mi++) {
                int ao = (wm + mi*16)*PADK + ks;
                wmma::load_matrix_sync(fah[mi], &Ah[ao], PADK);
                wmma::load_matrix_sync(fal[mi], &Al[ao], PADK);
            }
            #pragma unroll
            for (int ni = 0; ni < 2; ni++) {
                int bo = (wn + ni*16)*PADK + ks;
                wmma::load_matrix_sync(fbh[ni], &Bh2[bo], PADK);
                wmma::load_matrix_sync(fbl[ni], &Bl2[bo], PADK);
            }
            #pragma unroll
            for (int mi = 0; mi < 4; mi++) {
                #pragma unroll
                for (int ni = 0; ni < 2; ni++) {
                    wmma::mma_sync(acc[mi][ni], fah[mi], fbh[ni], acc[mi][ni]);
                    wmma::mma_sync(acc[mi][ni], fah[mi], fbl[ni], acc[mi][ni]);
                    wmma::mma_sync(acc[mi][ni], fal[mi], fbh[ni], acc[mi][ni]);
                }
            }
        }
    }

    __syncthreads();
    float* stage = (float*)Ah;
    float* ws = stage + wid*256;
    const int srow = lane >> 1;
    const int scol = (lane & 1)*8;
    for (int mi = 0; mi < 4; mi++) {
        for (int ni = 0; ni < 2; ni++) {
            wmma::store_matrix_sync(ws, acc[mi][ni], 16, wmma::mem_row_major);
            __syncwarp();
            int r = bm + wm + mi*16 + srow;
            int col = bn + wn + ni*16 + scol;
            float4 p0 = *(float4*)&ws[srow*16 + scol];
            float4 p1 = *(float4*)&ws[srow*16 + scol + 4];
            if (MODE == 0) {
                int which = col >> 10, c = col & 1023;
                float f = mask[r]*((which == 0) ? 0.125f : 1.f);
                __nv_bfloat16* dh = (which == 0) ? g_qh : ((which == 1) ? g_kh : g_vh);
                __nv_bfloat16* dl = (which == 0) ? g_ql : ((which == 1) ? g_kl : g_vl);
                int b = r >> 11, nq = r & 2047, h2 = c >> 6, d = c & 63;
                size_t off = ((size_t)(b*HEADS + h2)*NSEQ + nq)*HD + d;
                float vals[8];
                vals[0] = p0.x; vals[1] = p0.y; vals[2] = p0.z; vals[3] = p0.w;
                vals[4] = p1.x; vals[5] = p1.y; vals[6] = p1.z; vals[7] = p1.w;
                __nv_bfloat16 hh[8], ll[8];
                #pragma unroll
                for (int j = 0; j < 8; j++) {
                    float v = vals[j]*f;
                    __nv_bfloat16 hv = __float2bfloat16_rn(v);
                    hh[j] = hv;
                    ll[j] = __float2bfloat16_rn(v - __bfloat162float(hv));
                }
                *(uint4*)&dh[off] = *(uint4*)hh;
                *(uint4*)&dl[off] = *(uint4*)ll;
            } else {
                float4 b0 = *(const float4*)&bias[col];
                float4 b1 = *(const float4*)&bias[col+4];
                float* dp = out + (size_t)r*CDIM + col;
                *(float4*)dp = make_float4(p0.x+b0.x, p0.y+b0.y, p0.z+b0.z, p0.w+b0.w);
                *(float4*)(dp+4) = make_float4(p1.x+b1.x, p1.y+b1.y, p1.z+b1.z, p1.w+b1.w);
            }
            __syncwarp();
        }
    }
}

// prefetch one 64-row k-tile (KH,KL,VH,VL) into a smem buffer via cp.async
__device__ __forceinline__ void prefetch_tile(int tid, size_t base, int kt, __nv_bfloat16* buf) {
    #pragma unroll
    for (int t = 0; t < 8; t++) {
        int c = tid + t*256;
        int arr = c >> 9, rem = c & 511;
        int row = rem >> 3, seg = rem & 7;
        const __nv_bfloat16* src;
        if (arr == 0) src = g_kh;
        else if (arr == 1) src = g_kl;
        else if (arr == 2) src = g_vh;
        else src = g_vl;
        __pipeline_memcpy_async(buf + arr*KVB + row*KV_LD + seg*8,
                                src + base + (size_t)(kt + row)*HD + seg*8, 16);
    }
}

// tensor-core attention: 256 thr / 8 warps, 128 q-rows per CTA,
// double-buffered cp.async K/V tiles, warp-local S/exp/P phases.
__global__ __launch_bounds__(256, 1) void attn_mma(const float* __restrict__ mWin) {
    extern __shared__ char smraw[];
    __nv_bfloat16* KV = (__nv_bfloat16*)smraw;
    __nv_bfloat16* PH = KV + 2*BUFH;
    __nv_bfloat16* PL = PH + 128*KV_LD;
    float* SF = (float*)(PL + 128*KV_LD);
    float* DEN = SF + 128*SF_LD;

    const int tid = threadIdx.x, w = tid >> 5;
    const int bh = blockIdx.y, b = bh >> 4, h = bh & 15;
    const int q0 = blockIdx.x*128;
    const size_t base = (size_t)bh*NSEQ*HD;

    FA qfh[4], qfl[4];
    {
        const __nv_bfloat16* qp = g_qh + base + (size_t)(q0 + w*16)*HD;
        const __nv_bfloat16* qp2 = g_ql + base + (size_t)(q0 + w*16)*HD;
        #pragma unroll
        for (int kk = 0; kk < 4; kk++) {
            wmma::load_matrix_sync(qfh[kk], qp + kk*16, HD);
            wmma::load_matrix_sync(qfl[kk], qp2 + kk*16, HD);
        }
    }

    FC o[4];
    #pragma unroll
    for (int i = 0; i < 4; i++) wmma::fill_fragment(o[i], 0.f);
    float den = 0.f;
    const int erow = tid >> 1, ecol = (tid & 1)*32;

    prefetch_tile(tid, base, 0, KV);
    __pipeline_commit();

    for (int it = 0; it < 32; it++) {
        __syncthreads();
        if (it + 1 < 32) prefetch_tile(tid, base, (it+1)*64, KV + ((it+1)&1)*BUFH);
        __pipeline_commit();
        __pipeline_wait_prior(1);
        __syncthreads();

        __nv_bfloat16* KHb = KV + (it&1)*BUFH;
        __nv_bfloat16* KLb = KHb + KVB;
        __nv_bfloat16* VHb = KHb + 2*KVB;
        __nv_bfloat16* VLb = KHb + 3*KVB;

        #pragma unroll
        for (int n = 0; n < 4; n++) {
            FC s;
            wmma::fill_fragment(s, 0.f);
            #pragma unroll
            for (int kk = 0; kk < 4; kk++) {
                FBc kbh, kbl;
                wmma::load_matrix_sync(kbh, KHb + n*16*KV_LD + kk*16, KV_LD);
                wmma::load_matrix_sync(kbl, KLb + n*16*KV_LD + kk*16, KV_LD);
                wmma::mma_sync(s, qfh[kk], kbh, s);
                wmma::mma_sync(s, qfh[kk], kbl, s);
                wmma::mma_sync(s, qfl[kk], kbh, s);
            }
            wmma::store_matrix_sync(SF + w*16*SF_LD + n*16, s, SF_LD, wmma::mem_row_major);
        }
        __syncwarp();

        #pragma unroll
        for (int j = 0; j < 32; j += 2) {
            float2 sv = *(float2*)&SF[erow*SF_LD + ecol + j];
            float p0 = fexp(sv.x);
            float p1 = fexp(sv.y);
            den += p0 + p1;
            __nv_bfloat162 hi, lo;
            split2(p0, p1, hi, lo);
            *(__nv_bfloat162*)&PH[erow*KV_LD + ecol + j] = hi;
            *(__nv_bfloat162*)&PL[erow*KV_LD + ecol + j] = lo;
        }
        __syncwarp();

        FA pa[4], pb[4];
        #pragma unroll
        for (int kk = 0; kk < 4; kk++) {
            wmma::load_matrix_sync(pa[kk], PH + w*16*KV_LD + kk*16, KV_LD);
            wmma::load_matrix_sync(pb[kk], PL + w*16*KV_LD + kk*16, KV_LD);
        }
        #pragma unroll
        for (int nd = 0; nd < 4; nd++) {
            #pragma unroll
            for (int kk = 0; kk < 4; kk++) {
                FBr vbh, vbl;
                wmma::load_matrix_sync(vbh, VHb + kk*16*KV_LD + nd*16, KV_LD);
                wmma::load_matrix_sync(vbl, VLb + kk*16*KV_LD + nd*16, KV_LD);
                wmma::mma_sync(o[nd], pa[kk], vbh, o[nd]);
                wmma::mma_sync(o[nd], pa[kk], vbl, o[nd]);
                wmma::mma_sync(o[nd], pb[kk], vbh, o[nd]);
            }
        }
    }

    DEN[tid] = den;
    #pragma unroll
    for (int nd = 0; nd < 4; nd++)
        wmma::store_matrix_sync(SF + w*16*SF_LD + nd*16, o[nd], SF_LD, wmma::mem_row_major);
    __syncthreads();
    {
        int nq = q0 + erow;
        float dsum = DEN[erow*2] + DEN[erow*2+1];
        float mk = mWin[b*NSEQ + nq];
        float sc = 1.f/(dsum*(mk*g_msum[b] + 1e-6f));
        float* op = g_ao + (size_t)(b*NSEQ + nq)*CDIM + h*HD + ecol;
        #pragma unroll
        for (int j = 0; j < 32; j += 4) {
            float4 v = *(float4*)&SF[erow*SF_LD + ecol + j];
            *(float4*)&op[j] = make_float4(v.x*sc, v.y*sc, v.z*sc, v.w*sc);
        }
    }
}

extern "C" void kernel_launch(void* const* d_in, const int* in_sizes, int n_in,
                              void* d_out, int out_size) {
    const float* x = (const float*)d_in[0];
    const float* mWin = (const float*)d_in[1];
    const float* qkv_w = (const float*)d_in[2];
    const float* proj_w = (const float*)d_in[3];
    const float* proj_b = (const float*)d_in[4];
    float* out = (float*)d_out;

    const int attn_smem = (2*BUFH + 2*128*KV_LD)*2 + 128*SF_LD*4 + 256*4;
    cudaFuncSetAttribute(attn_mma, cudaFuncAttributeMaxDynamicSharedMemorySize, attn_smem);

    masksum_kernel<<<BATCH, 256>>>(mWin);
    wmma_gemm<0><<<dim3(3*CDIM/128, MTOT/128), 256>>>(x, qkv_w, CDIM, mWin, nullptr, nullptr);
    attn_mma<<<dim3(NSEQ/128, BH), 256, attn_smem>>>(mWin);
    wmma_gemm<1><<<dim3(CDIM/128, MTOT/128), 256>>>(nullptr, proj_w, CDIM, nullptr, proj_b, out);
}